// round 9
// baseline (speedup 1.0000x reference)
#include <cuda_runtime.h>

// PointPillarScatter: out[b,c,yi,xi] = feat[b,c,n*] where n* = max point index
// mapping to cell (yi,xi) in batch b (JAX scatter-set last-wins); 0 elsewhere.
// Index math replicates XLA: /0.16f -> *fp32(1/0.16f) == *6.25f exactly.
//
// Dirty-line-recycling round: scratch is a 51.2 MB buffer REUSED across the
// two batch-pairs. Pair-1's transpose overwrites pair-0's dirty scratch lines
// while they still sit in L2, eliminating their DRAM writeback; fill's
// gathers hit the L2-resident slice. Output uses __stcs, feat uses __ldcs so
// the streams don't evict the scratch.

namespace {
constexpr int B  = 4;
constexpr int C  = 64;
constexpr int N  = 100000;
constexpr int NY = 496;
constexpr int NX = 432;
constexpr int CELLS  = NY * NX;      // 214272
constexpr int VCELLS = CELLS / 4;    // 53568 (float4 granularity)
constexpr int HV     = VCELLS / 2;   // 26784 (split-half stride, cell-quads)
constexpr int SLOTS  = 16;           // 2 batches x 8 channel-groups per pair
}

// Scratch (no runtime allocation allowed).
__device__ __align__(16) int   g_winner[B * CELLS];
__device__ float g_minxy[B][2];
__device__ __align__(16) float g_srow[(size_t)SLOTS * N * 8];   // 51.2 MB, reused x2

__device__ __forceinline__ void atomicMinF(float* addr, float v) {
    if (v >= 0.0f) atomicMin((int*)addr, __float_as_int(v));
    else           atomicMax((unsigned int*)addr, __float_as_uint(v));
}

__global__ void pp_init() {
    int i = blockIdx.x * blockDim.x + threadIdx.x;
    if (i < B * VCELLS) reinterpret_cast<int4*>(g_winner)[i] = make_int4(-1, -1, -1, -1);
    if (i < B * 2) reinterpret_cast<float*>(g_minxy)[i] = __int_as_float(0x7f800000);
}

// Per-batch min over x,y. points row = [b, x, y, z] as float4.
__global__ void pp_min(const float4* __restrict__ pts) {
    const int b = blockIdx.y;
    const float INF = __int_as_float(0x7f800000);
    float mx = INF, my = INF;
    for (int n = blockIdx.x * blockDim.x + threadIdx.x; n < N; n += gridDim.x * blockDim.x) {
        float4 v = pts[b * N + n];
        mx = fminf(mx, v.y);
        my = fminf(my, v.z);
    }
    #pragma unroll
    for (int o = 16; o; o >>= 1) {
        mx = fminf(mx, __shfl_xor_sync(0xffffffffu, mx, o));
        my = fminf(my, __shfl_xor_sync(0xffffffffu, my, o));
    }
    __shared__ float sx[32], sy[32];
    const int warp = threadIdx.x >> 5, lane = threadIdx.x & 31;
    if (lane == 0) { sx[warp] = mx; sy[warp] = my; }
    __syncthreads();
    if (warp == 0) {
        const int nw = blockDim.x >> 5;
        mx = (lane < nw) ? sx[lane] : INF;
        my = (lane < nw) ? sy[lane] : INF;
        #pragma unroll
        for (int o = 16; o; o >>= 1) {
            mx = fminf(mx, __shfl_xor_sync(0xffffffffu, mx, o));
            my = fminf(my, __shfl_xor_sync(0xffffffffu, my, o));
        }
        if (lane == 0) {
            atomicMinF(&g_minxy[b][0], mx);
            atomicMinF(&g_minxy[b][1], my);
        }
    }
}

// Elect per-cell winner = max point index (JAX scatter-set last-wins).
__global__ void pp_winner(const float4* __restrict__ pts) {
    const int b = blockIdx.y;
    const float xmin = g_minxy[b][0];
    const float ymin = g_minxy[b][1];
    const int n = blockIdx.x * blockDim.x + threadIdx.x;
    if (n >= N) return;
    float4 v = pts[b * N + n];
    const float R = 6.25f;                 // fp32(1/0.16f) == 6.25f (XLA rewrite)
    int xi = (int)floorf((v.y - xmin) * R);
    int yi = (int)floorf((v.z - ymin) * R);
    xi = min(max(xi, 0), NX - 1);
    yi = min(max(yi, 0), NY - 1);
    atomicMax(&g_winner[b * CELLS + yi * NX + xi], n);
}

// Transpose for one batch-pair: srow[slot][n][k] = feat[b][g*8+k][n],
// slot = (b - pair*2)*8 + g. feat streamed __ldcs; scratch default policy
// (stays dirty in L2, recycled by the next pair's overwrite).
__global__ void __launch_bounds__(256) pp_transpose_pair(const float* __restrict__ feat, int pair) {
    int idx = blockIdx.x * blockDim.x + threadIdx.x;    // over SLOTS * N
    if (idx >= SLOTS * N) return;
    const int n    = idx % N;
    const int slot = idx / N;                           // (b_local)*8 + g
    const int b    = pair * 2 + (slot >> 3);
    const int g    = slot & 7;
    const float* fin = feat + ((size_t)b * C + (size_t)g * 8) * N;
    float v[8];
    #pragma unroll
    for (int k = 0; k < 8; ++k)
        v[k] = __ldcs(fin + (size_t)k * N + n);
    float4* o = reinterpret_cast<float4*>(g_srow) + (size_t)slot * N * 2;
    o[n * 2 + 0] = make_float4(v[0], v[1], v[2], v[3]);
    o[n * 2 + 1] = make_float4(v[4], v[5], v[6], v[7]);
}

// Fill for one batch-pair: per thread = (slot, cell-quads h and h+HV).
// Each cell's 8-channel row = two adjacent LDG.128 from the L2-resident
// scratch. Stores: 16 coalesced streaming STG.128.
__global__ void __launch_bounds__(256) pp_fill_pair(float4* __restrict__ out, int pair) {
    const int total = SLOTS * HV;
    int idx = blockIdx.x * blockDim.x + threadIdx.x;
    if (idx >= total) return;
    const int h    = idx % HV;
    const int slot = idx / HV;
    const int b    = pair * 2 + (slot >> 3);
    const int g    = slot & 7;
    const int4* wp = reinterpret_cast<const int4*>(g_winner) + b * VCELLS;
    int4 w0 = wp[h];
    int4 w1 = wp[h + HV];
    const float4* fp = reinterpret_cast<const float4*>(g_srow) + (size_t)slot * N * 2;
    const float4 z = make_float4(0.f, 0.f, 0.f, 0.f);
    float4 lo[8], hi[8];
    int wn[8] = {w0.x, w0.y, w0.z, w0.w, w1.x, w1.y, w1.z, w1.w};
    #pragma unroll
    for (int i = 0; i < 8; ++i) {
        lo[i] = (wn[i] >= 0) ? __ldg(fp + 2 * wn[i])     : z;
        hi[i] = (wn[i] >= 0) ? __ldg(fp + 2 * wn[i] + 1) : z;
    }
    float4* ob = out + ((size_t)b * C + (size_t)g * 8) * (CELLS / 4) / 1 * 1; // base of 8 planes
    // (CELLS/4) == VCELLS; expression kept simple below:
    ob = out + ((size_t)b * C + (size_t)g * 8) * VCELLS;
    #pragma unroll
    for (int k = 0; k < 4; ++k) {
        float4 s0, s1;
        s0 = make_float4(((const float*)&lo[0])[k], ((const float*)&lo[1])[k],
                         ((const float*)&lo[2])[k], ((const float*)&lo[3])[k]);
        s1 = make_float4(((const float*)&lo[4])[k], ((const float*)&lo[5])[k],
                         ((const float*)&lo[6])[k], ((const float*)&lo[7])[k]);
        __stcs(ob + (size_t)k * VCELLS + h,      s0);
        __stcs(ob + (size_t)k * VCELLS + h + HV, s1);
        s0 = make_float4(((const float*)&hi[0])[k], ((const float*)&hi[1])[k],
                         ((const float*)&hi[2])[k], ((const float*)&hi[3])[k]);
        s1 = make_float4(((const float*)&hi[4])[k], ((const float*)&hi[5])[k],
                         ((const float*)&hi[6])[k], ((const float*)&hi[7])[k]);
        __stcs(ob + (size_t)(k + 4) * VCELLS + h,      s0);
        __stcs(ob + (size_t)(k + 4) * VCELLS + h + HV, s1);
    }
}

extern "C" void kernel_launch(void* const* d_in, const int* in_sizes, int n_in,
                              void* d_out, int out_size) {
    (void)in_sizes; (void)n_in; (void)out_size;
    const float*  feat = (const float*)d_in[0];   // (B, C, N) f32
    const float4* pts  = (const float4*)d_in[1];  // (B*N, 4)  f32
    // d_in[2] (voxel_coords) unused by the reference computation.

    pp_init<<<(B * VCELLS + 255) / 256, 256>>>();
    pp_min<<<dim3(98, B), 256>>>(pts);
    pp_winner<<<dim3((N + 255) / 256, B), 256>>>(pts);
    for (int pair = 0; pair < 2; ++pair) {
        pp_transpose_pair<<<(SLOTS * N + 255) / 256, 256>>>(feat, pair);
        pp_fill_pair<<<(SLOTS * HV + 255) / 256, 256>>>((float4*)d_out, pair);
    }
}

// round 10
// speedup vs baseline: 1.3001x; 1.3001x over previous
#include <cuda_runtime.h>

// PointPillarScatter: out[b,c,yi,xi] = feat[b,c,n*] where n* = max point index
// mapping to cell (yi,xi) in batch b (JAX scatter-set last-wins); 0 elsewhere.
// Index math replicates XLA: /0.16f -> *fp32(1/0.16f) == *6.25f exactly.
//
// R3's exact kernels, split into two batch-pairs over a reused 51.2 MB
// scratch. Pair-1's transpose overwrites pair-0's dirty scratch lines in L2
// (writeback elided); fill's gathers hit the L2-resident slice. Output is
// written __stcs so its stream doesn't evict the scratch.

namespace {
constexpr int B  = 4;
constexpr int C  = 64;
constexpr int N  = 100000;
constexpr int NY = 496;
constexpr int NX = 432;
constexpr int CELLS  = NY * NX;      // 214272
constexpr int VCELLS = CELLS / 4;    // 53568 (float4 granularity)
constexpr int G      = B * (C / 4);  // 64 channel-quad groups total
constexpr int SLOTS  = G / 2;        // 32 groups per pair
constexpr int NV     = N / 4;        // 25000 point-quads
}

// Scratch (no runtime allocation allowed).
__device__ __align__(16) int   g_winner[B * CELLS];
__device__ float g_minxy[B][2];
__device__ __align__(16) float g_feat4[(size_t)SLOTS * N * 4];   // 51.2 MB, reused x2

__device__ __forceinline__ void atomicMinF(float* addr, float v) {
    if (v >= 0.0f) atomicMin((int*)addr, __float_as_int(v));
    else           atomicMax((unsigned int*)addr, __float_as_uint(v));
}

__global__ void pp_init() {
    int i = blockIdx.x * blockDim.x + threadIdx.x;
    if (i < B * VCELLS) reinterpret_cast<int4*>(g_winner)[i] = make_int4(-1, -1, -1, -1);
    if (i < B * 2) reinterpret_cast<float*>(g_minxy)[i] = __int_as_float(0x7f800000);
}

// Per-batch min over x,y. points row = [b, x, y, z] as float4.
__global__ void pp_min(const float4* __restrict__ pts) {
    const int b = blockIdx.y;
    const float INF = __int_as_float(0x7f800000);
    float mx = INF, my = INF;
    for (int n = blockIdx.x * blockDim.x + threadIdx.x; n < N; n += gridDim.x * blockDim.x) {
        float4 v = pts[b * N + n];
        mx = fminf(mx, v.y);
        my = fminf(my, v.z);
    }
    #pragma unroll
    for (int o = 16; o; o >>= 1) {
        mx = fminf(mx, __shfl_xor_sync(0xffffffffu, mx, o));
        my = fminf(my, __shfl_xor_sync(0xffffffffu, my, o));
    }
    __shared__ float sx[32], sy[32];
    const int warp = threadIdx.x >> 5, lane = threadIdx.x & 31;
    if (lane == 0) { sx[warp] = mx; sy[warp] = my; }
    __syncthreads();
    if (warp == 0) {
        const int nw = blockDim.x >> 5;
        mx = (lane < nw) ? sx[lane] : INF;
        my = (lane < nw) ? sy[lane] : INF;
        #pragma unroll
        for (int o = 16; o; o >>= 1) {
            mx = fminf(mx, __shfl_xor_sync(0xffffffffu, mx, o));
            my = fminf(my, __shfl_xor_sync(0xffffffffu, my, o));
        }
        if (lane == 0) {
            atomicMinF(&g_minxy[b][0], mx);
            atomicMinF(&g_minxy[b][1], my);
        }
    }
}

// Elect per-cell winner = max point index (JAX scatter-set last-wins).
__global__ void pp_winner(const float4* __restrict__ pts) {
    const int b = blockIdx.y;
    const float xmin = g_minxy[b][0];
    const float ymin = g_minxy[b][1];
    const int n = blockIdx.x * blockDim.x + threadIdx.x;
    if (n >= N) return;
    float4 v = pts[b * N + n];
    const float R = 6.25f;                 // fp32(1/0.16f) == 6.25f (XLA rewrite)
    int xi = (int)floorf((v.y - xmin) * R);
    int yi = (int)floorf((v.z - ymin) * R);
    xi = min(max(xi, 0), NX - 1);
    yi = min(max(yi, 0), NY - 1);
    atomicMax(&g_winner[b * CELLS + yi * NX + xi], n);
}

// R3's channel-interleave transpose, restricted to one batch-pair:
// feat4[slot][n][k] = feat[plane (pair*32+slot)*4 + k][n]. All global
// accesses fully coalesced (4 float4 loads + 4 float4 stores per thread).
__global__ void __launch_bounds__(256) pp_transpose_pair(const float* __restrict__ feat, int pair) {
    int idx = blockIdx.x * blockDim.x + threadIdx.x;    // over SLOTS * NV
    if (idx >= SLOTS * NV) return;
    const int nv   = idx % NV;
    const int slot = idx / NV;
    const int g    = pair * SLOTS + slot;               // global channel-quad
    const float4* base = reinterpret_cast<const float4*>(feat);
    const size_t row = (size_t)g * 4 * NV;
    float4 r0 = base[row + 0 * NV + nv];
    float4 r1 = base[row + 1 * NV + nv];
    float4 r2 = base[row + 2 * NV + nv];
    float4 r3 = base[row + 3 * NV + nv];
    float4* o = reinterpret_cast<float4*>(g_feat4) + (size_t)slot * N + nv * 4;
    o[0] = make_float4(r0.x, r1.x, r2.x, r3.x);
    o[1] = make_float4(r0.y, r1.y, r2.y, r3.y);
    o[2] = make_float4(r0.z, r1.z, r2.z, r3.z);
    o[3] = make_float4(r0.w, r1.w, r2.w, r3.w);
}

// R3's fill, restricted to one batch-pair. One 16B gather per (cell, 4ch)
// from the L2-resident scratch; output stores are streaming (__stcs).
__global__ void __launch_bounds__(256) pp_fill_pair(float4* __restrict__ out, int pair) {
    const int total = SLOTS * VCELLS;
    int idx = blockIdx.x * blockDim.x + threadIdx.x;
    if (idx >= total) return;
    const int v    = idx % VCELLS;
    const int slot = idx / VCELLS;
    const int g    = pair * SLOTS + slot;
    const int b    = g >> 4;                            // 16 quads per batch
    int4 w = reinterpret_cast<const int4*>(g_winner)[b * VCELLS + v];
    const float4* fp = reinterpret_cast<const float4*>(g_feat4) + (size_t)slot * N;
    const float4 z = make_float4(0.f, 0.f, 0.f, 0.f);
    float4 g0 = (w.x >= 0) ? __ldg(fp + w.x) : z;
    float4 g1 = (w.y >= 0) ? __ldg(fp + w.y) : z;
    float4 g2 = (w.z >= 0) ? __ldg(fp + w.z) : z;
    float4 g3 = (w.w >= 0) ? __ldg(fp + w.w) : z;
    float4* ob = out + (size_t)g * 4 * VCELLS + v;
    __stcs(ob + 0 * VCELLS, make_float4(g0.x, g1.x, g2.x, g3.x));
    __stcs(ob + 1 * VCELLS, make_float4(g0.y, g1.y, g2.y, g3.y));
    __stcs(ob + 2 * VCELLS, make_float4(g0.z, g1.z, g2.z, g3.z));
    __stcs(ob + 3 * VCELLS, make_float4(g0.w, g1.w, g2.w, g3.w));
}

extern "C" void kernel_launch(void* const* d_in, const int* in_sizes, int n_in,
                              void* d_out, int out_size) {
    (void)in_sizes; (void)n_in; (void)out_size;
    const float*  feat = (const float*)d_in[0];   // (B, C, N) f32
    const float4* pts  = (const float4*)d_in[1];  // (B*N, 4)  f32
    // d_in[2] (voxel_coords) unused by the reference computation.

    pp_init<<<(B * VCELLS + 255) / 256, 256>>>();
    pp_min<<<dim3(98, B), 256>>>(pts);
    pp_winner<<<dim3((N + 255) / 256, B), 256>>>(pts);
    for (int pair = 0; pair < 2; ++pair) {
        pp_transpose_pair<<<(SLOTS * NV + 255) / 256, 256>>>(feat, pair);
        pp_fill_pair<<<(SLOTS * VCELLS + 255) / 256, 256>>>((float4*)d_out, pair);
    }
}

// round 11
// speedup vs baseline: 1.3486x; 1.0373x over previous
#include <cuda_runtime.h>

// PointPillarScatter: out[b,c,yi,xi] = feat[b,c,n*] where n* = max point index
// mapping to cell (yi,xi) in batch b (JAX scatter-set last-wins); 0 elsewhere.
// Index math replicates XLA: /0.16f -> *fp32(1/0.16f) == *6.25f exactly.
//
// Pipelined single-launch overlap: pp_step(tb, fb) runs transpose(batch tb)
// and fill(batch fb) in ONE grid, blocks Bresenham-interleaved so the
// read-heavy transpose stream and write-heavy fill stream share the memory
// system. Scratch = 2 x 25.6 MB ping-pong (L2-resident; feat read __ldcs,
// output written __stcs so neither stream evicts it).

namespace {
constexpr int B  = 4;
constexpr int C  = 64;
constexpr int N  = 100000;
constexpr int NY = 496;
constexpr int NX = 432;
constexpr int CELLS  = NY * NX;        // 214272
constexpr int VCELLS = CELLS / 4;      // 53568 (float4 granularity)
constexpr int NV     = N / 4;          // 25000 point-quads
constexpr int SLOTS  = C / 4;          // 16 channel-quad groups per batch

constexpr int T_ITEMS  = SLOTS * NV;        // 400000
constexpr int F_ITEMS  = SLOTS * VCELLS;    // 857088
constexpr int T_BLOCKS = (T_ITEMS + 255) / 256;   // 1563
constexpr int F_BLOCKS = F_ITEMS / 256;           // 3348 (exact)
constexpr int TF_BLOCKS = T_BLOCKS + F_BLOCKS;    // 4911
}

// Scratch (no runtime allocation allowed).
__device__ __align__(16) int   g_winner[B * CELLS];
__device__ float g_minxy[B][2];
__device__ __align__(16) float g_buf[2][(size_t)SLOTS * N * 4];   // 2 x 25.6 MB

__device__ __forceinline__ void atomicMinF(float* addr, float v) {
    if (v >= 0.0f) atomicMin((int*)addr, __float_as_int(v));
    else           atomicMax((unsigned int*)addr, __float_as_uint(v));
}

__global__ void pp_init() {
    int i = blockIdx.x * blockDim.x + threadIdx.x;
    if (i < B * VCELLS) reinterpret_cast<int4*>(g_winner)[i] = make_int4(-1, -1, -1, -1);
    if (i < B * 2) reinterpret_cast<float*>(g_minxy)[i] = __int_as_float(0x7f800000);
}

// Per-batch min over x,y. points row = [b, x, y, z] as float4.
__global__ void pp_min(const float4* __restrict__ pts) {
    const int b = blockIdx.y;
    const float INF = __int_as_float(0x7f800000);
    float mx = INF, my = INF;
    for (int n = blockIdx.x * blockDim.x + threadIdx.x; n < N; n += gridDim.x * blockDim.x) {
        float4 v = pts[b * N + n];
        mx = fminf(mx, v.y);
        my = fminf(my, v.z);
    }
    #pragma unroll
    for (int o = 16; o; o >>= 1) {
        mx = fminf(mx, __shfl_xor_sync(0xffffffffu, mx, o));
        my = fminf(my, __shfl_xor_sync(0xffffffffu, my, o));
    }
    __shared__ float sx[32], sy[32];
    const int warp = threadIdx.x >> 5, lane = threadIdx.x & 31;
    if (lane == 0) { sx[warp] = mx; sy[warp] = my; }
    __syncthreads();
    if (warp == 0) {
        const int nw = blockDim.x >> 5;
        mx = (lane < nw) ? sx[lane] : INF;
        my = (lane < nw) ? sy[lane] : INF;
        #pragma unroll
        for (int o = 16; o; o >>= 1) {
            mx = fminf(mx, __shfl_xor_sync(0xffffffffu, mx, o));
            my = fminf(my, __shfl_xor_sync(0xffffffffu, my, o));
        }
        if (lane == 0) {
            atomicMinF(&g_minxy[b][0], mx);
            atomicMinF(&g_minxy[b][1], my);
        }
    }
}

// Elect per-cell winner = max point index (JAX scatter-set last-wins).
__global__ void pp_winner(const float4* __restrict__ pts) {
    const int b = blockIdx.y;
    const float xmin = g_minxy[b][0];
    const float ymin = g_minxy[b][1];
    const int n = blockIdx.x * blockDim.x + threadIdx.x;
    if (n >= N) return;
    float4 v = pts[b * N + n];
    const float R = 6.25f;                 // fp32(1/0.16f) == 6.25f (XLA rewrite)
    int xi = (int)floorf((v.y - xmin) * R);
    int yi = (int)floorf((v.z - ymin) * R);
    xi = min(max(xi, 0), NX - 1);
    yi = min(max(yi, 0), NY - 1);
    atomicMax(&g_winner[b * CELLS + yi * NX + xi], n);
}

// Transpose role: feat[b][slot*4+k][n] -> buf[b&1][slot][n][k] (16B rows).
// All global accesses fully coalesced; feat streamed (__ldcs).
__device__ __forceinline__ void t_body(const float* __restrict__ feat, int b, int blk) {
    int idx = blk * 256 + threadIdx.x;
    if (idx >= T_ITEMS) return;
    const int nv   = idx % NV;
    const int slot = idx / NV;
    const float4* base = reinterpret_cast<const float4*>(feat);
    const size_t row = ((size_t)b * C + slot * 4) * NV;
    float4 r0 = __ldcs(base + row + 0 * NV + nv);
    float4 r1 = __ldcs(base + row + 1 * NV + nv);
    float4 r2 = __ldcs(base + row + 2 * NV + nv);
    float4 r3 = __ldcs(base + row + 3 * NV + nv);
    float4* o = reinterpret_cast<float4*>(g_buf[b & 1]) + (size_t)slot * N + nv * 4;
    o[0] = make_float4(r0.x, r1.x, r2.x, r3.x);
    o[1] = make_float4(r0.y, r1.y, r2.y, r3.y);
    o[2] = make_float4(r0.z, r1.z, r2.z, r3.z);
    o[3] = make_float4(r0.w, r1.w, r2.w, r3.w);
}

// Fill role: one 16B gather per (cell, 4ch) from the L2-resident scratch;
// 4 streaming coalesced STG.128 per thread.
__device__ __forceinline__ void f_body(float4* __restrict__ out, int b, int blk) {
    int idx = blk * 256 + threadIdx.x;          // always < F_ITEMS (exact grid)
    const int v    = idx % VCELLS;
    const int slot = idx / VCELLS;
    int4 w = reinterpret_cast<const int4*>(g_winner)[b * VCELLS + v];
    const float4* fp = reinterpret_cast<const float4*>(g_buf[b & 1]) + (size_t)slot * N;
    const float4 z = make_float4(0.f, 0.f, 0.f, 0.f);
    float4 g0 = (w.x >= 0) ? __ldg(fp + w.x) : z;
    float4 g1 = (w.y >= 0) ? __ldg(fp + w.y) : z;
    float4 g2 = (w.z >= 0) ? __ldg(fp + w.z) : z;
    float4 g3 = (w.w >= 0) ? __ldg(fp + w.w) : z;
    float4* ob = out + ((size_t)b * C + slot * 4) * VCELLS + v;
    __stcs(ob + 0 * VCELLS, make_float4(g0.x, g1.x, g2.x, g3.x));
    __stcs(ob + 1 * VCELLS, make_float4(g0.y, g1.y, g2.y, g3.y));
    __stcs(ob + 2 * VCELLS, make_float4(g0.z, g1.z, g2.z, g3.z));
    __stcs(ob + 3 * VCELLS, make_float4(g0.w, g1.w, g2.w, g3.w));
}

// One pipeline step: transpose(tb) and/or fill(fb), blocks interleaved
// Bresenham-style so both roles are resident on every SM simultaneously.
__global__ void __launch_bounds__(256) pp_step(const float* __restrict__ feat,
                                               float4* __restrict__ out,
                                               int tb, int fb) {
    const int bx = blockIdx.x;
    if (tb >= 0 && fb >= 0) {
        // Interleave: exactly T_BLOCKS of TF_BLOCKS are T-role, evenly spread.
        int tBefore = (int)(((long long)bx * T_BLOCKS) / TF_BLOCKS);
        int tNext   = (int)(((long long)(bx + 1) * T_BLOCKS) / TF_BLOCKS);
        if (tNext > tBefore) t_body(feat, tb, tBefore);
        else                 f_body(out, fb, bx - tBefore);
    } else if (tb >= 0) {
        t_body(feat, tb, bx);
    } else {
        f_body(out, fb, bx);
    }
}

extern "C" void kernel_launch(void* const* d_in, const int* in_sizes, int n_in,
                              void* d_out, int out_size) {
    (void)in_sizes; (void)n_in; (void)out_size;
    const float*  feat = (const float*)d_in[0];   // (B, C, N) f32
    const float4* pts  = (const float4*)d_in[1];  // (B*N, 4)  f32
    float4* out = (float4*)d_out;
    // d_in[2] (voxel_coords) unused by the reference computation.

    pp_init<<<(B * VCELLS + 255) / 256, 256>>>();
    pp_min<<<dim3(98, B), 256>>>(pts);
    pp_winner<<<dim3((N + 255) / 256, B), 256>>>(pts);

    pp_step<<<T_BLOCKS, 256>>>(feat, out, 0, -1);            // T0
    pp_step<<<TF_BLOCKS, 256>>>(feat, out, 1, 0);            // T1 || F0
    pp_step<<<TF_BLOCKS, 256>>>(feat, out, 2, 1);            // T2 || F1
    pp_step<<<TF_BLOCKS, 256>>>(feat, out, 3, 2);            // T3 || F2
    pp_step<<<F_BLOCKS, 256>>>(feat, out, -1, 3);            // F3
}